// round 6
// baseline (speedup 1.0000x reference)
#include <cuda_runtime.h>
#include <math.h>

#define Bb 64
#define Tt 12
#define Nn 512
#define Dd 2
#define Rr 64
#define NB (Nn*Bb)   // 32768 rows (row = n*64 + b)

// ---------------- device scratch ----------------
__device__ float g_h[2][NB*Rr];      // ping-pong hidden state
__device__ float g_s[NB*Rr];         // s = A^T h
__device__ float g_W2[130*192];      // [k][plane*64+g]; k<64: W_hh, 64..127: combo, 128..129: Wx
__device__ float g_cvec[192];        // b_msg @ W_ih_m^T
__device__ float g_csum[Nn];         // column sums of adj_pos
__device__ int   g_colj[Nn*Nn];      // CSC: column i at [i*512 ..]
__device__ float g_colw[Nn*Nn];
__device__ int   g_cnt[Nn];

// ---------------- f32x2 helpers ----------------
typedef unsigned long long ull;
#define FMA2(d, a, b) asm("fma.rn.f32x2 %0, %1, %2, %0;" : "+l"(d) : "l"(a), "l"(b))
#define PACK2(o, f)   asm("mov.b64 %0, {%1, %1};" : "=l"(o) : "f"(f))
#define UNPACK2(lo, hi, v) asm("mov.b64 {%0, %1}, %2;" : "=f"(lo), "=f"(hi) : "l"(v))

// ---------------- prep ----------------
__global__ void prep_kernel(const float* __restrict__ W_hh,
                            const float* __restrict__ W_ih,
                            const float* __restrict__ W_msg,
                            const float* __restrict__ b_msg) {
    int idx = blockIdx.x * 256 + threadIdx.x;
    if (idx < 12288) {                       // h-part: [k][o] = W_hh[o][k]
        int k = idx / 192, o = idx - k*192;
        g_W2[idx] = W_hh[o*64 + k];
    } else if (idx < 24576) {                // s-part: combo[ks][o]
        int j = idx - 12288;
        int ks = j / 192, o = j - ks*192;
        float s = 0.f;
        for (int m = 0; m < 64; m++) s += W_msg[m*64 + ks] * W_ih[o*66 + m];
        g_W2[idx] = s;
    } else if (idx < 24576 + 384) {          // x rows: [128+d][o] = W_ih[o][64+d]
        int j = idx - 24576;
        int d = j / 192, o = j - d*192;
        g_W2[(128 + d)*192 + o] = W_ih[o*66 + 64 + d];
    } else if (idx < 24960 + 192) {          // cvec[o] = sum_m b_msg[m]*W_ih[o][m]
        int o = idx - 24960;
        float s = 0.f;
        for (int m = 0; m < 64; m++) s += b_msg[m] * W_ih[o*66 + m];
        g_cvec[o] = s;
    }
}

// Deterministic CSC build + column sums.
__global__ void build_csc(const float* __restrict__ adj) {
    int i = blockIdx.x;
    int j = threadIdx.x;                      // 512 threads
    float w = adj[j*Nn + i];
    bool p = (w > 0.f);
    unsigned mask = __ballot_sync(0xffffffffu, p);
    int warp = j >> 5, lane = j & 31;
    __shared__ int wcnt[16];
    __shared__ int wofs[16];
    __shared__ float ws[512];
    ws[j] = p ? w : 0.f;
    if (lane == 0) wcnt[warp] = __popc(mask);
    __syncthreads();
    if (j == 0) {
        int s = 0;
        for (int t = 0; t < 16; t++) { wofs[t] = s; s += wcnt[t]; }
        g_cnt[i] = s;
    }
    for (int stride = 256; stride > 0; stride >>= 1) {
        __syncthreads();
        if (j < stride) ws[j] += ws[j + stride];
    }
    if (j == 0) g_csum[i] = ws[0];
    __syncthreads();
    if (p) {
        int pos = wofs[warp] + __popc(mask & ((1u << lane) - 1u));
        g_colj[i*Nn + pos] = j;
        g_colw[i*Nn + pos] = w;
    }
}

// ---------------- per step kernel 1: s = A^T h ----------------
__global__ __launch_bounds__(256, 3)
void agg_kernel(const float* __restrict__ h0, int t) {
    extern __shared__ float hS[];   // [512][32]
    const float* __restrict__ hsrc = (t == 0) ? h0 : g_h[t & 1];
    int bid = blockIdx.x;
    int b = bid & 63, mc = (bid >> 6) & 1, iq = bid >> 7;
    int tid = threadIdx.x;

    for (int idx = tid; idx < Nn*8; idx += 256) {
        int j = idx >> 3, q = idx & 7;
        ((float4*)hS)[idx] = *(const float4*)(hsrc + (((j << 6) + b) << 6) + (mc << 5) + (q << 2));
    }
    __syncthreads();

    int lane = tid & 31, wid = tid >> 5;
    #pragma unroll 1
    for (int c = 0; c < 16; c++) {
        int i = (iq << 7) + (c << 3) + wid;
        int cnt = g_cnt[i];
        const int*   cj = g_colj + i*Nn;
        const float* cw = g_colw + i*Nn;
        float a0=0.f,a1=0.f,a2=0.f,a3=0.f,a4=0.f,a5=0.f,a6=0.f,a7=0.f;
        int e = 0;
        for (; e + 8 <= cnt; e += 8) {
            int4   j0 = *(const int4*)(cj + e);
            int4   j1 = *(const int4*)(cj + e + 4);
            float4 w0 = *(const float4*)(cw + e);
            float4 w1 = *(const float4*)(cw + e + 4);
            a0 += w0.x * hS[(j0.x << 5) + lane];
            a1 += w0.y * hS[(j0.y << 5) + lane];
            a2 += w0.z * hS[(j0.z << 5) + lane];
            a3 += w0.w * hS[(j0.w << 5) + lane];
            a4 += w1.x * hS[(j1.x << 5) + lane];
            a5 += w1.y * hS[(j1.y << 5) + lane];
            a6 += w1.z * hS[(j1.z << 5) + lane];
            a7 += w1.w * hS[(j1.w << 5) + lane];
        }
        for (; e < cnt; e++)
            a0 += cw[e] * hS[(cj[e] << 5) + lane];
        g_s[(((i << 6) + b) << 6) + (mc << 5) + lane] =
            ((a0 + a1) + (a2 + a3)) + ((a4 + a5) + (a6 + a7));
    }
}

// ---------------- per step kernel 2: fused GEMM + GRU ----------------
// grid 1024 = (n:512) x (gate-half:2); 128 threads; block: 64 rows x 96 outs.
// thread: 4 rows x 4 gates x 4 acc-planes = 32 packed f32x2 accumulators.
// Single pass: h-weights + s-weights both resident in smem.
#define HP 68
__global__ __launch_bounds__(128, 2)
void gru_kernel(const float* __restrict__ inputs,
                const float* __restrict__ b_ih,
                const float* __restrict__ b_hh,
                const float* __restrict__ h0,
                int t) {
    extern __shared__ float sm[];
    float* wS = sm;                 // [130][96] = 12480 : [k][plane*32+gl]
    float* hT = sm + 12480;         // [64][HP]
    float* sT = hT + 64*HP;         // [66][HP] (rows 64,65 = x)
    float* tb = sT + 66*HP;         // 576: bi(192) | bh(192) | cv(192)

    const float* __restrict__ hsrc = (t == 0) ? h0 : g_h[t & 1];
    float* __restrict__ hdst = g_h[(t + 1) & 1];

    int n = blockIdx.x >> 1;
    int gbase = (blockIdx.x & 1) << 5;   // 0 or 32 (per-plane gate offset)
    int rowBase = n << 6;
    int tid = threadIdx.x;

    for (int idx = tid; idx < 4096; idx += 128) {
        int r = idx >> 6, k = idx & 63;
        hT[k*HP + r] = hsrc[(rowBase + r)*64 + k];
        sT[k*HP + r] = g_s[(rowBase + r)*64 + k];
    }
    if (tid < 64) {
        float2 x = *(const float2*)(inputs + ((tid*Tt + t)*Nn + n)*Dd);
        sT[64*HP + tid] = x.x;
        sT[65*HP + tid] = x.y;
    }
    for (int idx = tid; idx < 12480; idx += 128) {
        int k = idx / 96;
        int c = idx - k*96;
        int plane = c >> 5, gl = c & 31;
        wS[idx] = g_W2[k*192 + plane*64 + gbase + gl];
    }
    for (int idx = tid; idx < 576; idx += 128) {
        float v = (idx < 192) ? b_ih[idx]
                : (idx < 384) ? b_hh[idx - 192]
                : g_cvec[idx - 384];
        tb[idx] = v;
    }
    __syncthreads();

    int tx = tid & 7, ty = tid >> 3;     // 8 gate-cols x 16 row-groups
    int r0 = ty << 2;                    // 4 rows
    int gofs = tx << 2;                  // 4 gates (within 32-gate half)

    ull aR[4][2], aZ[4][2], aN1[4][2], aN2[4][2];
    #pragma unroll
    for (int rr = 0; rr < 4; rr++) {
        aR[rr][0]=0; aR[rr][1]=0; aZ[rr][0]=0; aZ[rr][1]=0;
        aN1[rr][0]=0; aN1[rr][1]=0; aN2[rr][0]=0; aN2[rr][1]=0;
    }

    // h-part: planes r,z,hn
    #pragma unroll 2
    for (int k = 0; k < 64; k++) {
        const float* wk = wS + k*96 + gofs;
        ulonglong2 wr = *(const ulonglong2*)(wk);
        ulonglong2 wz = *(const ulonglong2*)(wk + 32);
        ulonglong2 wn = *(const ulonglong2*)(wk + 64);
        float4 hv4 = *(const float4*)(hT + k*HP + r0);
        #pragma unroll
        for (int rr = 0; rr < 4; rr++) {
            float hv = (rr==0)?hv4.x:(rr==1)?hv4.y:(rr==2)?hv4.z:hv4.w;
            ull h2; PACK2(h2, hv);
            FMA2(aR[rr][0],  h2, wr.x); FMA2(aR[rr][1],  h2, wr.y);
            FMA2(aZ[rr][0],  h2, wz.x); FMA2(aZ[rr][1],  h2, wz.y);
            FMA2(aN1[rr][0], h2, wn.x); FMA2(aN1[rr][1], h2, wn.y);
        }
    }
    // s-part (+x rows 64,65): planes r,z,in
    #pragma unroll 2
    for (int k = 0; k < 66; k++) {
        const float* wk = wS + (64 + k)*96 + gofs;
        ulonglong2 wr = *(const ulonglong2*)(wk);
        ulonglong2 wz = *(const ulonglong2*)(wk + 32);
        ulonglong2 wn = *(const ulonglong2*)(wk + 64);
        float4 sv4 = *(const float4*)(sT + k*HP + r0);
        #pragma unroll
        for (int rr = 0; rr < 4; rr++) {
            float sv = (rr==0)?sv4.x:(rr==1)?sv4.y:(rr==2)?sv4.z:sv4.w;
            ull s2; PACK2(s2, sv);
            FMA2(aR[rr][0],  s2, wr.x); FMA2(aR[rr][1],  s2, wr.y);
            FMA2(aZ[rr][0],  s2, wz.x); FMA2(aZ[rr][1],  s2, wz.y);
            FMA2(aN2[rr][0], s2, wn.x); FMA2(aN2[rr][1], s2, wn.y);
        }
    }

    // epilogue: biases + cvec + GRU nonlinearity
    float cs = g_csum[n];
    #pragma unroll
    for (int rr = 0; rr < 4; rr++) {
        int rloc = r0 + rr;
        int row = rowBase + rloc;
        float vR[4], vZ[4], vN1[4], vN2[4], hnew[4];
        UNPACK2(vR[0],  vR[1],  aR[rr][0]);  UNPACK2(vR[2],  vR[3],  aR[rr][1]);
        UNPACK2(vZ[0],  vZ[1],  aZ[rr][0]);  UNPACK2(vZ[2],  vZ[3],  aZ[rr][1]);
        UNPACK2(vN1[0], vN1[1], aN1[rr][0]); UNPACK2(vN1[2], vN1[3], aN1[rr][1]);
        UNPACK2(vN2[0], vN2[1], aN2[rr][0]); UNPACK2(vN2[2], vN2[3], aN2[rr][1]);
        #pragma unroll
        for (int j = 0; j < 4; j++) {
            int g = gbase + gofs + j;        // per-plane gate index 0..63
            float rpre = vR[j]  + tb[g]        + tb[192 + g]        + cs*tb[384 + g];
            float zpre = vZ[j]  + tb[64 + g]   + tb[192 + 64 + g]   + cs*tb[384 + 64 + g];
            float inp  = vN2[j] + tb[128 + g]                        + cs*tb[384 + 128 + g];
            float hnp  = vN1[j] + tb[192 + 128 + g];
            float rg = 1.f / (1.f + expf(-rpre));
            float zg = 1.f / (1.f + expf(-zpre));
            float nn = tanhf(inp + rg*hnp);
            float hold = hT[g*HP + rloc];
            hnew[j] = (1.f - zg)*nn + zg*hold;
        }
        *(float4*)(hdst + row*64 + gbase + gofs) = *(float4*)hnew;
    }
}

// ---------------- final readout ----------------
__global__ void out_kernel(const float* __restrict__ W_out,
                           const float* __restrict__ b_out,
                           float* __restrict__ out) {
    __shared__ float wo[12*64];
    __shared__ float bo[12];
    int tid = threadIdx.x;
    for (int idx = tid; idx < 768; idx += 256) wo[idx] = W_out[idx];
    if (tid < 12) bo[tid] = b_out[tid];
    __syncthreads();
    int row = blockIdx.x * 256 + tid;
    float accs[12];
    #pragma unroll
    for (int hh = 0; hh < 12; hh++) accs[hh] = bo[hh];
    for (int k = 0; k < 64; k++) {
        float hv = g_h[0][row*64 + k];
        #pragma unroll
        for (int hh = 0; hh < 12; hh++) accs[hh] += hv * wo[hh*64 + k];
    }
    int n = row >> 6, b = row & 63;
    #pragma unroll
    for (int hh = 0; hh < 12; hh++)
        out[(b*12 + hh)*512 + n] = accs[hh];
}

extern "C" void kernel_launch(void* const* d_in, const int* in_sizes, int n_in,
                              void* d_out, int out_size) {
    const float* inputs = (const float*)d_in[0];
    const float* h0     = (const float*)d_in[1];
    const float* adj    = (const float*)d_in[2];
    const float* W_msg  = (const float*)d_in[3];
    const float* b_msg  = (const float*)d_in[4];
    const float* W_ih   = (const float*)d_in[5];
    const float* W_hh   = (const float*)d_in[6];
    const float* b_ih   = (const float*)d_in[7];
    const float* b_hh   = (const float*)d_in[8];
    const float* W_out  = (const float*)d_in[9];
    const float* b_out  = (const float*)d_in[10];
    float* out = (float*)d_out;

    static const int GRU_SMEM = (12480 + 64*HP + 66*HP + 576) * 4;   // 87584 B
    cudaFuncSetAttribute(gru_kernel, cudaFuncAttributeMaxDynamicSharedMemorySize, GRU_SMEM);
    cudaFuncSetAttribute(agg_kernel, cudaFuncAttributeMaxDynamicSharedMemorySize, 65536);

    prep_kernel<<<99, 256>>>(W_hh, W_ih, W_msg, b_msg);
    build_csc<<<512, 512>>>(adj);

    // t=11 writes g_h[0]; out_kernel reads g_h[0].
    for (int t = 0; t < Tt; t++) {
        agg_kernel<<<512, 256, 65536>>>(h0, t);
        gru_kernel<<<1024, 128, GRU_SMEM>>>(inputs, b_ih, b_hh, h0, t);
    }
    out_kernel<<<128, 256>>>(W_out, b_out, out);
}

// round 8
// speedup vs baseline: 1.4114x; 1.4114x over previous
#include <cuda_runtime.h>
#include <cuda_bf16.h>
#include <math.h>
#include <stdint.h>

#define Bb 64
#define Tt 12
#define Nn 512
#define Dd 2
#define NB (Nn*Bb)   // 32768 rows (row = node*64 + batch)

// ---------------- device scratch ----------------
__device__ float g_h[2][NB*64];          // ping-pong hidden state
__device__ float g_s[NB*64];             // s = A^T h
// B fragments, packed for mma.m16n8k16 row.col: [split][ktile 8][ntile 32][lane 32][reg 2]
__device__ uint32_t g_Bp[2*8*32*64];
__device__ float g_cvec[192];            // b_msg @ W_ih_m^T
__device__ float g_Wx[384];              // x weights [d][o]
__device__ float g_csum[Nn];
__device__ int   g_colj[Nn*Nn];
__device__ float g_colw[Nn*Nn];
__device__ int   g_cnt[Nn];

__device__ __forceinline__ uint32_t packbf(__nv_bfloat16 lo, __nv_bfloat16 hi) {
    return ((uint32_t)__bfloat16_as_ushort(hi) << 16) | (uint32_t)__bfloat16_as_ushort(lo);
}
__device__ __forceinline__ void split2(float v, __nv_bfloat16& b1, __nv_bfloat16& b2) {
    b1 = __float2bfloat16_rn(v);
    b2 = __float2bfloat16_rn(v - __bfloat162float(b1));
}

#define MMA16816(c, a, b) \
    asm volatile("mma.sync.aligned.m16n8k16.row.col.f32.bf16.bf16.f32 " \
        "{%0,%1,%2,%3}, {%4,%5,%6,%7}, {%8,%9}, {%0,%1,%2,%3};" \
        : "+f"((c)[0]), "+f"((c)[1]), "+f"((c)[2]), "+f"((c)[3]) \
        : "r"((a)[0]), "r"((a)[1]), "r"((a)[2]), "r"((a)[3]), \
          "r"((b)[0]), "r"((b)[1]))

// ---------------- prep: pack B fragments + tables ----------------
// B matrix: W[n][k], n = plane*64+gate (planes r,z,nh,ns), k<64: h-weights, k>=64: s-weights.
__global__ void prep_kernel(const float* __restrict__ W_hh,
                            const float* __restrict__ W_ih,
                            const float* __restrict__ W_msg,
                            const float* __restrict__ b_msg) {
    int idx = blockIdx.x * 256 + threadIdx.x;
    if (idx < 16384) {                      // (n 0..255) x (kpair 0..63)
        int n = idx >> 6, kp = idx & 63;
        int p = n >> 6, g = n & 63;
        float w[2];
        #pragma unroll
        for (int u = 0; u < 2; u++) {
            int k = 2*kp + u;
            float v = 0.f;
            if (k < 64) {
                if (p < 3) v = W_hh[(p*64 + g)*64 + k];
            } else {
                int ks = k - 64;
                if (p != 2) {
                    int o = (p == 3) ? (128 + g) : (p*64 + g);
                    float s = 0.f;
                    for (int m = 0; m < 64; m++) s += W_msg[m*64 + ks] * W_ih[o*66 + m];
                    v = s;
                }
            }
            w[u] = v;
        }
        __nv_bfloat16 lo1, lo2, hi1, hi2;
        split2(w[0], lo1, lo2);
        split2(w[1], hi1, hi2);
        int nt = n >> 3, kt = kp >> 3, q = kp & 7;
        int lane = ((n & 7) << 2) + (q & 3);
        int reg = q >> 2;
        g_Bp[((0*8 + kt)*32 + nt)*64 + lane*2 + reg] = packbf(lo1, hi1);
        g_Bp[((1*8 + kt)*32 + nt)*64 + lane*2 + reg] = packbf(lo2, hi2);
    } else if (idx < 16384 + 384) {          // Wx[d][o]
        int j = idx - 16384;
        int d = j / 192, o = j - d*192;
        g_Wx[j] = W_ih[o*66 + 64 + d];
    } else if (idx < 16384 + 384 + 192) {    // cvec
        int o = idx - 16384 - 384;
        float s = 0.f;
        for (int m = 0; m < 64; m++) s += b_msg[m] * W_ih[o*66 + m];
        g_cvec[o] = s;
    }
}

// ---------------- deterministic CSC build + column sums ----------------
__global__ void build_csc(const float* __restrict__ adj) {
    int i = blockIdx.x;
    int j = threadIdx.x;
    float w = adj[j*Nn + i];
    bool p = (w > 0.f);
    unsigned mask = __ballot_sync(0xffffffffu, p);
    int warp = j >> 5, lane = j & 31;
    __shared__ int wcnt[16];
    __shared__ int wofs[16];
    __shared__ float ws[512];
    ws[j] = p ? w : 0.f;
    if (lane == 0) wcnt[warp] = __popc(mask);
    __syncthreads();
    if (j == 0) {
        int s = 0;
        for (int t = 0; t < 16; t++) { wofs[t] = s; s += wcnt[t]; }
        g_cnt[i] = s;
    }
    for (int stride = 256; stride > 0; stride >>= 1) {
        __syncthreads();
        if (j < stride) ws[j] += ws[j + stride];
    }
    if (j == 0) g_csum[i] = ws[0];
    __syncthreads();
    if (p) {
        int pos = wofs[warp] + __popc(mask & ((1u << lane) - 1u));
        g_colj[i*Nn + pos] = j;
        g_colw[i*Nn + pos] = w;
    }
}

// ---------------- per step kernel 1: s = A^T h ----------------
__global__ __launch_bounds__(256, 3)
void agg_kernel(const float* __restrict__ h0, int t) {
    extern __shared__ float hS[];   // [512][32]
    const float* __restrict__ hsrc = (t == 0) ? h0 : g_h[t & 1];
    int bid = blockIdx.x;
    int b = bid & 63, mc = (bid >> 6) & 1, iq = bid >> 7;
    int tid = threadIdx.x;

    for (int idx = tid; idx < Nn*8; idx += 256) {
        int j = idx >> 3, q = idx & 7;
        ((float4*)hS)[idx] = *(const float4*)(hsrc + (((j << 6) + b) << 6) + (mc << 5) + (q << 2));
    }
    __syncthreads();

    int lane = tid & 31, wid = tid >> 5;
    #pragma unroll 1
    for (int c = 0; c < 16; c++) {
        int i = (iq << 7) + (c << 3) + wid;
        int cnt = g_cnt[i];
        const int*   cj = g_colj + i*Nn;
        const float* cw = g_colw + i*Nn;
        float a0=0.f,a1=0.f,a2=0.f,a3=0.f,a4=0.f,a5=0.f,a6=0.f,a7=0.f;
        int e = 0;
        for (; e + 8 <= cnt; e += 8) {
            int4   j0 = *(const int4*)(cj + e);
            int4   j1 = *(const int4*)(cj + e + 4);
            float4 w0 = *(const float4*)(cw + e);
            float4 w1 = *(const float4*)(cw + e + 4);
            a0 += w0.x * hS[(j0.x << 5) + lane];
            a1 += w0.y * hS[(j0.y << 5) + lane];
            a2 += w0.z * hS[(j0.z << 5) + lane];
            a3 += w0.w * hS[(j0.w << 5) + lane];
            a4 += w1.x * hS[(j1.x << 5) + lane];
            a5 += w1.y * hS[(j1.y << 5) + lane];
            a6 += w1.z * hS[(j1.z << 5) + lane];
            a7 += w1.w * hS[(j1.w << 5) + lane];
        }
        for (; e < cnt; e++)
            a0 += cw[e] * hS[(cj[e] << 5) + lane];
        g_s[(((i << 6) + b) << 6) + (mc << 5) + lane] =
            ((a0 + a1) + (a2 + a3)) + ((a4 + a5) + (a6 + a7));
    }
}

// ---------------- per step kernel 2: HMMA GEMM + GRU epilogue ----------------
// grid 512 (node n = 64 rows each); 256 threads = 8 warps.
// C[64,256] = A[64,128] x W^T via 3 bf16-split MMA combos.
// warp w: rows mw*32 (mw=w&1), cols nw*64 (nw=w>>1).
#define CP 260
__global__ __launch_bounds__(256, 2)
void gru_mma_kernel(const float* __restrict__ inputs,
                    const float* __restrict__ b_ih,
                    const float* __restrict__ b_hh,
                    const float* __restrict__ h0,
                    int t) {
    extern __shared__ char smc[];
    float* tb = (float*)smc;                       // 960 floats
    uint32_t* apack = (uint32_t*)(smc + 3840);     // [s][mt4][kt8][lane32][reg4] = 32KB
    float* Cbuf = (float*)(smc + 3840);            // [64][CP] fp32 (aliases apack)

    const float* __restrict__ hsrc = (t == 0) ? h0 : g_h[t & 1];
    float* __restrict__ hdst = g_h[(t + 1) & 1];

    int n = blockIdx.x;
    int rowBase = n << 6;
    int tid = threadIdx.x;

    // tables
    for (int idx = tid; idx < 960; idx += 256) {
        float v = (idx < 192) ? b_ih[idx]
                : (idx < 384) ? b_hh[idx - 192]
                : (idx < 576) ? g_cvec[idx - 384]
                : g_Wx[idx - 576];
        tb[idx] = v;
    }
    // A staging: split [h|s] rows into 2 bf16 components, pack into fragment layout
    for (int it = 0; it < 16; it++) {
        int item = tid + it*256;            // (r 0..63) x (kp 0..63)
        int r = item >> 6, kp = item & 63;
        int rowg = rowBase + r;
        const float* src = (kp < 32) ? (hsrc + rowg*64 + 2*kp)
                                     : (g_s + rowg*64 + 2*kp - 64);
        float2 v = *(const float2*)src;
        __nv_bfloat16 lo1, lo2, hi1, hi2;
        split2(v.x, lo1, lo2);
        split2(v.y, hi1, hi2);
        int mt = r >> 4, kt = kp >> 3, q = kp & 7;
        int lane = ((r & 7) << 2) + (q & 3);
        int reg = ((q >> 2) << 1) + ((r & 15) >> 3);
        apack[((0*4 + mt)*8 + kt)*128 + lane*4 + reg] = packbf(lo1, hi1);
        apack[((1*4 + mt)*8 + kt)*128 + lane*4 + reg] = packbf(lo2, hi2);
    }
    __syncthreads();

    int lane = tid & 31;
    int w = tid >> 5;
    int mw = w & 1, nw = w >> 1;

    float c[2][8][4];
    #pragma unroll
    for (int i = 0; i < 2; i++)
        #pragma unroll
        for (int j = 0; j < 8; j++)
            #pragma unroll
            for (int q = 0; q < 4; q++) c[i][j][q] = 0.f;

    const uint32_t* __restrict__ Bp = g_Bp;
    #pragma unroll 1
    for (int combo = 0; combo < 3; combo++) {
        int sa = (combo == 2) ? 1 : 0;
        int sb = (combo == 1) ? 1 : 0;
        #pragma unroll 2
        for (int kt = 0; kt < 8; kt++) {
            uint32_t a[2][4];
            #pragma unroll
            for (int mt2 = 0; mt2 < 2; mt2++)
                *(uint4*)a[mt2] = *(const uint4*)(apack +
                    ((sa*4 + mw*2 + mt2)*8 + kt)*128 + lane*4);
            uint32_t b[8][2];
            const uint32_t* bp = Bp + ((sb*8 + kt)*32 + nw*8)*64 + lane*2;
            #pragma unroll
            for (int nt2 = 0; nt2 < 8; nt2++)
                *(uint2*)b[nt2] = *(const uint2*)(bp + nt2*64);
            #pragma unroll
            for (int mt2 = 0; mt2 < 2; mt2++)
                #pragma unroll
                for (int nt2 = 0; nt2 < 8; nt2++)
                    MMA16816(c[mt2][nt2], a[mt2], b[nt2]);
        }
    }
    __syncthreads();   // apack reads done before Cbuf overwrite

    // write C fragments to smem
    {
        int g = lane >> 2, tg = lane & 3;
        #pragma unroll
        for (int mt2 = 0; mt2 < 2; mt2++) {
            int mrow = mw*32 + mt2*16 + g;
            #pragma unroll
            for (int nt2 = 0; nt2 < 8; nt2++) {
                int col = nw*64 + nt2*8 + tg*2;
                *(float2*)(Cbuf + mrow*CP + col)       = make_float2(c[mt2][nt2][0], c[mt2][nt2][1]);
                *(float2*)(Cbuf + (mrow + 8)*CP + col) = make_float2(c[mt2][nt2][2], c[mt2][nt2][3]);
            }
        }
    }
    __syncthreads();

    // GRU epilogue: thread handles row = tid>>2, gates (tid&3)*16 .. +15
    {
        int row = tid >> 2;
        int gbase = (tid & 3) << 4;
        int rowg = rowBase + row;
        float cs = g_csum[n];
        const float* xp = inputs + ((row*Tt + t)*Nn + n)*Dd;   // b = row
        float x0 = xp[0], x1 = xp[1];
        const float* Crow = Cbuf + row*CP;
        float hn[16];
        #pragma unroll
        for (int j = 0; j < 16; j++) {
            int g = gbase + j;
            float vr  = Crow[g]        + tb[g]       + tb[192 + g]
                      + cs*tb[384 + g] + x0*tb[576 + g] + x1*tb[768 + g];
            float vz  = Crow[64 + g]   + tb[64 + g]  + tb[256 + g]
                      + cs*tb[448 + g] + x0*tb[640 + g] + x1*tb[832 + g];
            float vnh = Crow[128 + g]  + tb[320 + g];
            float vns = Crow[192 + g]  + tb[128 + g]
                      + cs*tb[512 + g] + x0*tb[704 + g] + x1*tb[896 + g];
            float rg = 1.f / (1.f + expf(-vr));
            float zg = 1.f / (1.f + expf(-vz));
            float nn = tanhf(vns + rg*vnh);
            hn[j] = (1.f - zg)*nn + zg*hsrc[rowg*64 + g];
        }
        #pragma unroll
        for (int j = 0; j < 4; j++)
            *(float4*)(hdst + rowg*64 + gbase + j*4) = *(float4*)(hn + j*4);
    }
}

// ---------------- final readout ----------------
__global__ void out_kernel(const float* __restrict__ W_out,
                           const float* __restrict__ b_out,
                           float* __restrict__ out) {
    __shared__ float wo[12*64];
    __shared__ float bo[12];
    int tid = threadIdx.x;
    for (int idx = tid; idx < 768; idx += 256) wo[idx] = W_out[idx];
    if (tid < 12) bo[tid] = b_out[tid];
    __syncthreads();
    int row = blockIdx.x * 256 + tid;
    float accs[12];
    #pragma unroll
    for (int hh = 0; hh < 12; hh++) accs[hh] = bo[hh];
    for (int k = 0; k < 64; k++) {
        float hv = g_h[0][row*64 + k];
        #pragma unroll
        for (int hh = 0; hh < 12; hh++) accs[hh] += hv * wo[hh*64 + k];
    }
    int n = row >> 6, b = row & 63;
    #pragma unroll
    for (int hh = 0; hh < 12; hh++)
        out[(b*12 + hh)*512 + n] = accs[hh];
}

extern "C" void kernel_launch(void* const* d_in, const int* in_sizes, int n_in,
                              void* d_out, int out_size) {
    const float* inputs = (const float*)d_in[0];
    const float* h0     = (const float*)d_in[1];
    const float* adj    = (const float*)d_in[2];
    const float* W_msg  = (const float*)d_in[3];
    const float* b_msg  = (const float*)d_in[4];
    const float* W_ih   = (const float*)d_in[5];
    const float* W_hh   = (const float*)d_in[6];
    const float* b_ih   = (const float*)d_in[7];
    const float* b_hh   = (const float*)d_in[8];
    const float* W_out  = (const float*)d_in[9];
    const float* b_out  = (const float*)d_in[10];
    float* out = (float*)d_out;

    static const int MMA_SMEM = 3840 + 64*CP*4;   // 3840 + 66560 = 70400 B
    cudaFuncSetAttribute(gru_mma_kernel, cudaFuncAttributeMaxDynamicSharedMemorySize, MMA_SMEM);
    cudaFuncSetAttribute(agg_kernel,     cudaFuncAttributeMaxDynamicSharedMemorySize, 65536);

    prep_kernel<<<67, 256>>>(W_hh, W_ih, W_msg, b_msg);
    build_csc<<<512, 512>>>(adj);

    // t=11 writes g_h[0]; out_kernel reads g_h[0].
    for (int t = 0; t < Tt; t++) {
        agg_kernel<<<512, 256, 65536>>>(h0, t);
        gru_mma_kernel<<<512, 256, MMA_SMEM>>>(inputs, b_ih, b_hh, h0, t);
    }
    out_kernel<<<128, 256>>>(W_out, b_out, out);
}